// round 3
// baseline (speedup 1.0000x reference)
#include <cuda_runtime.h>
#include <math.h>

// Problem constants (fixed by setup_inputs)
#define NSPK 2048
#define MUTT 8
#define DEMB 512
#define NMROWS (NSPK * MUTT)   // 16384

// Scratch: normalized centroids [NSPK][DEMB], leave-one-out diagonal sims [NMROWS]
__device__ float g_cent[NSPK * DEMB];
__device__ float g_diag[NMROWS];

// ---------------------------------------------------------------------------
// Kernel 1: centroids + leave-one-out diagonal scalars. One warp per speaker.
//   s = sum_m e_m ;  centroid = s/||s||
//   diag_m = (p_m - q_m) / sqrt(ns - 2 p_m + q_m),  p_m = e_m.s, q_m = e_m.e_m, ns = s.s
// Also zeroes the output accumulator (runs before kernel 2 in stream order).
// ---------------------------------------------------------------------------
__global__ void __launch_bounds__(256) centroid_kernel(const float* __restrict__ E,
                                                       float* __restrict__ out) {
    if (blockIdx.x == 0 && threadIdx.x == 0) out[0] = 0.0f;

    int warp = (blockIdx.x * blockDim.x + threadIdx.x) >> 5;
    int lane = threadIdx.x & 31;
    if (warp >= NSPK) return;

    const float* e = E + (size_t)warp * (MUTT * DEMB);

    // Each lane owns 16 d-indices: lane*4 + c*128 + {0..3}, c = 0..3
    float4 s[4];
#pragma unroll
    for (int c = 0; c < 4; c++) s[c] = make_float4(0.f, 0.f, 0.f, 0.f);

    float q[MUTT];
#pragma unroll
    for (int m = 0; m < MUTT; m++) {
        q[m] = 0.f;
#pragma unroll
        for (int c = 0; c < 4; c++) {
            float4 v = *(const float4*)(e + m * DEMB + c * 128 + lane * 4);
            s[c].x += v.x; s[c].y += v.y; s[c].z += v.z; s[c].w += v.w;
            q[m] += v.x * v.x + v.y * v.y + v.z * v.z + v.w * v.w;
        }
    }

    float p[MUTT];
#pragma unroll
    for (int m = 0; m < MUTT; m++) {
        p[m] = 0.f;
#pragma unroll
        for (int c = 0; c < 4; c++) {
            float4 v = *(const float4*)(e + m * DEMB + c * 128 + lane * 4);  // L1 hit
            p[m] += v.x * s[c].x + v.y * s[c].y + v.z * s[c].z + v.w * s[c].w;
        }
    }

    float ns = 0.f;
#pragma unroll
    for (int c = 0; c < 4; c++)
        ns += s[c].x * s[c].x + s[c].y * s[c].y + s[c].z * s[c].z + s[c].w * s[c].w;

    // Warp reductions (all lanes end with the full values)
#pragma unroll
    for (int off = 16; off > 0; off >>= 1) {
#pragma unroll
        for (int m = 0; m < MUTT; m++) {
            p[m] += __shfl_xor_sync(0xffffffffu, p[m], off);
            q[m] += __shfl_xor_sync(0xffffffffu, q[m], off);
        }
        ns += __shfl_xor_sync(0xffffffffu, ns, off);
    }

    float inv = rsqrtf(ns);
#pragma unroll
    for (int c = 0; c < 4; c++) {
        float4 cv = make_float4(s[c].x * inv, s[c].y * inv, s[c].z * inv, s[c].w * inv);
        *(float4*)(g_cent + (size_t)warp * DEMB + c * 128 + lane * 4) = cv;
    }

    if (lane < MUTT) {
        float pm = p[lane], qm = q[lane];
        g_diag[warp * MUTT + lane] = (pm - qm) * rsqrtf(ns - 2.f * pm + qm);
    }
}

// ---------------------------------------------------------------------------
// Kernel 2: fused [16384x512] x [512x2048]^T GEMM + per-row online logsumexp CE.
// Block tile 128 rows x 128 cols, k-tile 16, 256 threads, 8x8 micro-tiles.
// Each block sweeps all 16 column tiles for its rows, maintaining running
// (max, sumexp) per row; diagonal column patched to precomputed diag value.
// ---------------------------------------------------------------------------
#define BR 128
#define BC 128
#define KT 16

__global__ void __launch_bounds__(256, 1) gemm_loss_kernel(const float* __restrict__ A,
                                                           const float* __restrict__ wp,
                                                           const float* __restrict__ bp,
                                                           float* __restrict__ out) {
    __shared__ float As[KT][BR + 4];   // [k][row], padded stride 132
    __shared__ float Bs[KT][BC + 4];   // [k][col]
    __shared__ float red[16];

    int tid = threadIdx.x;
    int tx = tid & 15;        // column group (8 cols each)
    int ty = tid >> 4;        // row group    (8 rows each)
    int r0 = blockIdx.x * BR;
    int rowbase = r0 + ty * 8;

    float wabs = fabsf(wp[0]);
    float bb = bp[0];

    // Own-speaker logit (diag), pre-scaled
    float dval[8];
#pragma unroll
    for (int i = 0; i < 8; i++) dval[i] = wabs * g_diag[rowbase + i] + bb;

    float mrun[8], srun[8];
#pragma unroll
    for (int i = 0; i < 8; i++) { mrun[i] = -1e30f; srun[i] = 0.f; }

    for (int c0 = 0; c0 < NSPK; c0 += BC) {
        float acc[8][8];
#pragma unroll
        for (int i = 0; i < 8; i++)
#pragma unroll
            for (int j = 0; j < 8; j++) acc[i][j] = 0.f;

        for (int k0 = 0; k0 < DEMB; k0 += KT) {
            // Load tiles (transposed into [k][row|col]); 2 float4 per thread per tile
#pragma unroll
            for (int j = 0; j < 2; j++) {
                int i4 = tid + j * 256;          // 0..511
                int row = i4 >> 2;               // 0..127
                int c4 = i4 & 3;                 // k chunk
                float4 va = *(const float4*)(A + (size_t)(r0 + row) * DEMB + k0 + c4 * 4);
                As[c4 * 4 + 0][row] = va.x;
                As[c4 * 4 + 1][row] = va.y;
                As[c4 * 4 + 2][row] = va.z;
                As[c4 * 4 + 3][row] = va.w;
                float4 vb = *(const float4*)(g_cent + (size_t)(c0 + row) * DEMB + k0 + c4 * 4);
                Bs[c4 * 4 + 0][row] = vb.x;
                Bs[c4 * 4 + 1][row] = vb.y;
                Bs[c4 * 4 + 2][row] = vb.z;
                Bs[c4 * 4 + 3][row] = vb.w;
            }
            __syncthreads();

#pragma unroll
            for (int kk = 0; kk < KT; kk++) {
                float4 a0 = *(const float4*)(&As[kk][ty * 8]);
                float4 a1 = *(const float4*)(&As[kk][ty * 8 + 4]);
                float4 b0 = *(const float4*)(&Bs[kk][tx * 8]);
                float4 b1 = *(const float4*)(&Bs[kk][tx * 8 + 4]);
                float av[8] = {a0.x, a0.y, a0.z, a0.w, a1.x, a1.y, a1.z, a1.w};
                float bv[8] = {b0.x, b0.y, b0.z, b0.w, b1.x, b1.y, b1.z, b1.w};
#pragma unroll
                for (int i = 0; i < 8; i++)
#pragma unroll
                    for (int j = 0; j < 8; j++) acc[i][j] = fmaf(av[i], bv[j], acc[i][j]);
            }
            __syncthreads();
        }

        // Epilogue: scale/bias, diag patch, online logsumexp across this col tile
        int colbase = c0 + tx * 8;
#pragma unroll
        for (int i = 0; i < 8; i++) {
            int spk = (rowbase + i) >> 3;  // own-speaker column for this row (M=8)
            float z[8];
#pragma unroll
            for (int j = 0; j < 8; j++) z[j] = fmaf(wabs, acc[i][j], bb);
            int dcol = spk - colbase;
            if (dcol >= 0 && dcol < 8) z[dcol] = dval[i];

            float tm = z[0];
#pragma unroll
            for (int j = 1; j < 8; j++) tm = fmaxf(tm, z[j]);
#pragma unroll
            for (int off = 8; off > 0; off >>= 1)
                tm = fmaxf(tm, __shfl_xor_sync(0xffffffffu, tm, off));

            float nm = fmaxf(mrun[i], tm);
            float ts = 0.f;
#pragma unroll
            for (int j = 0; j < 8; j++) ts += __expf(z[j] - nm);
#pragma unroll
            for (int off = 8; off > 0; off >>= 1)
                ts += __shfl_xor_sync(0xffffffffu, ts, off);

            srun[i] = srun[i] * __expf(mrun[i] - nm) + ts;
            mrun[i] = nm;
        }
    }

    // Per-row loss = logsumexp - own logit; sum within block, atomic to out
    if (tx == 0) {
        float lsum = 0.f;
#pragma unroll
        for (int i = 0; i < 8; i++) lsum += logf(srun[i]) + mrun[i] - dval[i];
        red[ty] = lsum;
    }
    __syncthreads();
    if (tid == 0) {
        float t = 0.f;
#pragma unroll
        for (int k = 0; k < 16; k++) t += red[k];
        atomicAdd(out, t * (1.0f / (float)NMROWS));
    }
}

extern "C" void kernel_launch(void* const* d_in, const int* in_sizes, int n_in,
                              void* d_out, int out_size) {
    const float* E = (const float*)d_in[0];
    const float* w = (const float*)d_in[1];
    const float* b = (const float*)d_in[2];
    float* out = (float*)d_out;

    centroid_kernel<<<256, 256>>>(E, out);                    // 2048 warps = 1/speaker
    gemm_loss_kernel<<<NMROWS / BR, 256>>>(E, w, b, out);     // 128 blocks
}

// round 10
// speedup vs baseline: 14.8860x; 14.8860x over previous
#include <cuda_runtime.h>
#include <cuda_bf16.h>
#include <math.h>
#include <stdint.h>

// Problem constants (fixed by setup_inputs)
#define NSPK 2048
#define MUTT 8
#define DEMB 512
#define NMROWS (NSPK * MUTT)   // 16384

// tcgen05 is sm_103a/sm_100a arch-SPECIFIC. The harness build includes a
// family-portable compute_103 pass where these instructions are illegal PTX,
// so gate them on the arch-feature macros and fall back to SIMT FFMA there.
#if defined(__CUDA_ARCH__) && \
    (defined(__CUDA_ARCH_FEAT_SM103_ALL) || defined(__CUDA_ARCH_FEAT_SM100_ALL) || \
     defined(__CUDA_ARCH_FEAT_SM101_ALL))
#define USE_TCGEN05 1
#else
#define USE_TCGEN05 0
#endif

// Scratch: bf16 normalized centroids, fp32 leave-one-out diagonal sims
__device__ __nv_bfloat16 g_cent_bf[NSPK * DEMB];
__device__ float g_diag[NMROWS];

// ===========================================================================
// PTX helpers (guarded)
// ===========================================================================
__device__ __forceinline__ uint32_t smem_u32(const void* p) {
    uint32_t a;
    asm("{ .reg .u64 t; cvta.to.shared.u64 t, %1; cvt.u32.u64 %0, t; }"
        : "=r"(a) : "l"(p));
    return a;
}

#if USE_TCGEN05
__device__ __forceinline__ uint32_t elect_one() {
    uint32_t p;
    asm volatile("{\n\t.reg .pred p;\n\telect.sync _|p, 0xFFFFFFFF;\n\t"
                 "selp.b32 %0, 1, 0, p;\n\t}" : "=r"(p));
    return p;
}

#define TCGEN05_ALLOC(smem_addr, nCols) \
    asm volatile("tcgen05.alloc.cta_group::1.sync.aligned.shared::cta.b32 [%0], %1;" \
                 :: "r"((uint32_t)(smem_addr)), "r"((uint32_t)(nCols)) : "memory")
#define TCGEN05_DEALLOC(tmem, nCols) \
    asm volatile("tcgen05.dealloc.cta_group::1.sync.aligned.b32 %0, %1;" \
                 :: "r"(tmem), "r"((uint32_t)(nCols)))
#define TCGEN05_RELINQUISH() \
    asm volatile("tcgen05.relinquish_alloc_permit.cta_group::1.sync.aligned;")
#define TCGEN05_WAIT_ST() asm volatile("tcgen05.wait::st.sync.aligned;" ::: "memory")
#define TCGEN05_WAIT_LD() asm volatile("tcgen05.wait::ld.sync.aligned;" ::: "memory")
#define TCGEN05_FENCE_BEFORE() asm volatile("tcgen05.fence::before_thread_sync;" ::: "memory")
#define TCGEN05_FENCE_AFTER()  asm volatile("tcgen05.fence::after_thread_sync;" ::: "memory")
#define FENCE_PROXY_ASYNC() asm volatile("fence.proxy.async.shared::cta;" ::: "memory")
#define TCGEN05_COMMIT(mbar) \
    asm volatile("tcgen05.commit.cta_group::1.mbarrier::arrive::one.shared::cluster.b64 [%0];" \
                 :: "r"((uint32_t)(mbar)) : "memory")
#define MBARRIER_INIT(mbar, cnt) \
    asm volatile("mbarrier.init.shared.b64 [%0], %1;" \
                 :: "r"((uint32_t)(mbar)), "r"((uint32_t)(cnt)) : "memory")
#define MBARRIER_INVAL(mbar) \
    asm volatile("mbarrier.inval.shared.b64 [%0];" :: "r"((uint32_t)(mbar)) : "memory")

#define MBARRIER_WAIT_PARITY(mbar, parity) do {                                   \
    uint32_t _m = (uint32_t)(mbar); uint32_t _p = (uint32_t)(parity);             \
    asm volatile(                                                                 \
        "{\n\t.reg .pred P1;\n\t"                                                 \
        "WAIT_LOOP_%=:\n\t"                                                       \
        "mbarrier.try_wait.parity.acquire.cta.shared::cta.b64 P1, [%0], %1, 0x989680;\n\t" \
        "@P1 bra.uni WAIT_DONE_%=;\n\t"                                           \
        "bra.uni WAIT_LOOP_%=;\n\t"                                               \
        "WAIT_DONE_%=:\n\t}"                                                      \
        :: "r"(_m), "r"(_p) : "memory");                                          \
} while (0)

#define TCGEN05_MMA_F16(d_tmem, a_tmem, b_desc, idesc, enable_d) do {             \
    uint32_t _en = (enable_d) ? 1u : 0u; uint32_t _z = 0u;                        \
    asm volatile(                                                                 \
        "{\n\t.reg .pred p;\n\tsetp.ne.u32 p, %6, 0;\n\t"                         \
        "tcgen05.mma.cta_group::1.kind::f16 [%0], [%1], %2, %3, "                 \
        "{%4, %4, %4, %4}, p;\n\t}"                                               \
        :: "r"(d_tmem), "r"(a_tmem), "l"(b_desc), "r"(idesc),                     \
           "r"(_z), "r"(_z), "r"(_en) : "memory");                                \
} while (0)

#define TCGEN05_ST_X64(tmem_addr, r)                                              \
    asm volatile("tcgen05.st.sync.aligned.32x32b.x64.b32 [%0], "                  \
        "{%1, %2, %3, %4, %5, %6, %7, %8, "                                       \
        " %9, %10, %11, %12, %13, %14, %15, %16, "                                \
        " %17, %18, %19, %20, %21, %22, %23, %24, "                               \
        " %25, %26, %27, %28, %29, %30, %31, %32, "                               \
        " %33, %34, %35, %36, %37, %38, %39, %40, "                               \
        " %41, %42, %43, %44, %45, %46, %47, %48, "                               \
        " %49, %50, %51, %52, %53, %54, %55, %56, "                               \
        " %57, %58, %59, %60, %61, %62, %63, %64};"                               \
        :: "r"(tmem_addr),                                                        \
           "r"((r)[0]),  "r"((r)[1]),  "r"((r)[2]),  "r"((r)[3]),                 \
           "r"((r)[4]),  "r"((r)[5]),  "r"((r)[6]),  "r"((r)[7]),                 \
           "r"((r)[8]),  "r"((r)[9]),  "r"((r)[10]), "r"((r)[11]),                \
           "r"((r)[12]), "r"((r)[13]), "r"((r)[14]), "r"((r)[15]),                \
           "r"((r)[16]), "r"((r)[17]), "r"((r)[18]), "r"((r)[19]),                \
           "r"((r)[20]), "r"((r)[21]), "r"((r)[22]), "r"((r)[23]),                \
           "r"((r)[24]), "r"((r)[25]), "r"((r)[26]), "r"((r)[27]),                \
           "r"((r)[28]), "r"((r)[29]), "r"((r)[30]), "r"((r)[31]),                \
           "r"((r)[32]), "r"((r)[33]), "r"((r)[34]), "r"((r)[35]),                \
           "r"((r)[36]), "r"((r)[37]), "r"((r)[38]), "r"((r)[39]),                \
           "r"((r)[40]), "r"((r)[41]), "r"((r)[42]), "r"((r)[43]),                \
           "r"((r)[44]), "r"((r)[45]), "r"((r)[46]), "r"((r)[47]),                \
           "r"((r)[48]), "r"((r)[49]), "r"((r)[50]), "r"((r)[51]),                \
           "r"((r)[52]), "r"((r)[53]), "r"((r)[54]), "r"((r)[55]),                \
           "r"((r)[56]), "r"((r)[57]), "r"((r)[58]), "r"((r)[59]),                \
           "r"((r)[60]), "r"((r)[61]), "r"((r)[62]), "r"((r)[63])                 \
        : "memory")

#define TCGEN05_LD_X32(r, tmem_addr)                                              \
    asm volatile("tcgen05.ld.sync.aligned.32x32b.x32.b32 "                        \
        "{%0, %1, %2, %3, %4, %5, %6, %7, "                                       \
        " %8, %9, %10, %11, %12, %13, %14, %15, "                                 \
        " %16, %17, %18, %19, %20, %21, %22, %23, "                               \
        " %24, %25, %26, %27, %28, %29, %30, %31}, [%32];"                        \
        : "=r"((r)[0]),  "=r"((r)[1]),  "=r"((r)[2]),  "=r"((r)[3]),              \
          "=r"((r)[4]),  "=r"((r)[5]),  "=r"((r)[6]),  "=r"((r)[7]),              \
          "=r"((r)[8]),  "=r"((r)[9]),  "=r"((r)[10]), "=r"((r)[11]),             \
          "=r"((r)[12]), "=r"((r)[13]), "=r"((r)[14]), "=r"((r)[15]),             \
          "=r"((r)[16]), "=r"((r)[17]), "=r"((r)[18]), "=r"((r)[19]),             \
          "=r"((r)[20]), "=r"((r)[21]), "=r"((r)[22]), "=r"((r)[23]),             \
          "=r"((r)[24]), "=r"((r)[25]), "=r"((r)[26]), "=r"((r)[27]),             \
          "=r"((r)[28]), "=r"((r)[29]), "=r"((r)[30]), "=r"((r)[31])              \
        : "r"(tmem_addr))

// SMEM descriptor: SW128, version 1, SBO=64 (1024B per 8-row group), LBO=1
#define SMEM_DESC_BASE ((2ull << 61) | (1ull << 46) | (64ull << 32) | (1ull << 16))
#endif  // USE_TCGEN05

// ===========================================================================
// Kernel 1: centroids (bf16 out) + exact fp32 leave-one-out diag. Warp/speaker.
// ===========================================================================
__global__ void __launch_bounds__(256) centroid_kernel(const float* __restrict__ E,
                                                       float* __restrict__ out) {
    if (blockIdx.x == 0 && threadIdx.x == 0) out[0] = 0.0f;

    int warp = (blockIdx.x * blockDim.x + threadIdx.x) >> 5;
    int lane = threadIdx.x & 31;
    if (warp >= NSPK) return;

    const float* e = E + (size_t)warp * (MUTT * DEMB);

    float4 s[4];
#pragma unroll
    for (int c = 0; c < 4; c++) s[c] = make_float4(0.f, 0.f, 0.f, 0.f);

    float q[MUTT];
#pragma unroll
    for (int m = 0; m < MUTT; m++) {
        q[m] = 0.f;
#pragma unroll
        for (int c = 0; c < 4; c++) {
            float4 v = *(const float4*)(e + m * DEMB + c * 128 + lane * 4);
            s[c].x += v.x; s[c].y += v.y; s[c].z += v.z; s[c].w += v.w;
            q[m] += v.x * v.x + v.y * v.y + v.z * v.z + v.w * v.w;
        }
    }
    float p[MUTT];
#pragma unroll
    for (int m = 0; m < MUTT; m++) {
        p[m] = 0.f;
#pragma unroll
        for (int c = 0; c < 4; c++) {
            float4 v = *(const float4*)(e + m * DEMB + c * 128 + lane * 4);
            p[m] += v.x * s[c].x + v.y * s[c].y + v.z * s[c].z + v.w * s[c].w;
        }
    }
    float ns = 0.f;
#pragma unroll
    for (int c = 0; c < 4; c++)
        ns += s[c].x * s[c].x + s[c].y * s[c].y + s[c].z * s[c].z + s[c].w * s[c].w;

#pragma unroll
    for (int off = 16; off > 0; off >>= 1) {
#pragma unroll
        for (int m = 0; m < MUTT; m++) {
            p[m] += __shfl_xor_sync(0xffffffffu, p[m], off);
            q[m] += __shfl_xor_sync(0xffffffffu, q[m], off);
        }
        ns += __shfl_xor_sync(0xffffffffu, ns, off);
    }

    float inv = rsqrtf(ns);
#pragma unroll
    for (int c = 0; c < 4; c++) {
        __nv_bfloat162 h0 = __float22bfloat162_rn(make_float2(s[c].x * inv, s[c].y * inv));
        __nv_bfloat162 h1 = __float22bfloat162_rn(make_float2(s[c].z * inv, s[c].w * inv));
        uint32_t u0 = *(uint32_t*)&h0, u1 = *(uint32_t*)&h1;
        *(uint2*)(g_cent_bf + (size_t)warp * DEMB + c * 128 + lane * 4) = make_uint2(u0, u1);
    }
    if (lane < MUTT) {
        float pm = p[lane], qm = q[lane];
        g_diag[warp * MUTT + lane] = (pm - qm) * rsqrtf(ns - 2.f * pm + qm);
    }
}

// ===========================================================================
// Kernel 2 (shared launch config: grid 128, block 256, dynamic smem)
//   sm_103a pass: tcgen05 TS-mode bf16 GEMM + fused sum-exp CE epilogue
//   portable pass: SIMT FFMA tiled GEMM + fused online-logsumexp (round-3)
// ===========================================================================
#define BROWS 128
#define NB 64
#define NCHUNK (NSPK / NB)     // 32
#define KSTEPS (DEMB / 16)     // 32
#define MMA_IDESC 0x8100490u   // f32 acc, bf16 A/B, K-major, M=128, N=64

// shared memory offsets (dynamic smem; buffers 1024B-aligned from base)
#define SM_TMEMPTR 0
#define SM_MBAR0   8
#define SM_BUF0    2048
#define SM_RED     (2048 + 131072)      // 256 floats
#define SM_WS      (SM_RED + 1024)      // 4 floats
#define SMEM_TOTAL (SM_WS + 64)

// TMEM columns: A = [0,256), D0 = [256,320), D1 = [320,384)
#define TM_A  0
#define TM_D0 256

#if USE_TCGEN05
__device__ __forceinline__ void load_B_chunk(char* smem, int bufoff, int chunk, int tid) {
    const uint4* g = (const uint4*)(g_cent_bf + (size_t)chunk * NB * DEMB);
#pragma unroll
    for (int i = 0; i < 16; i++) {
        int lin = tid + i * 256;                 // uint4 (8 bf16) index, 0..4095
        int brow = lin >> 6;                     // centroid row in chunk, 0..63
        int kc = (lin & 63) << 3;                // bf16 k-column, multiple of 8
        // blocked SW128 atom layout: atom = 8 rows x 64 bf16, 8 atom-rows/col
        uint32_t off = (uint32_t)((brow >> 3) + ((kc >> 6) << 3)) * 1024u
                     + (uint32_t)(brow & 7) * 128u + (uint32_t)(kc & 63) * 2u;
        off ^= ((off >> 3) & 0x70u);             // SW128 swizzle
        *(uint4*)(smem + bufoff + off) = g[lin];
    }
}
#endif

__global__ void __launch_bounds__(256, 1) gemm_loss_kernel(const float* __restrict__ E,
                                                           const float* __restrict__ wp,
                                                           const float* __restrict__ bp,
                                                           float* __restrict__ out) {
    extern __shared__ char smem[];
#if USE_TCGEN05
    // ---------------- tcgen05 path (runs on the GB300) ----------------
    uint32_t smem_base = smem_u32(smem);
    int tid = threadIdx.x;
    int wid = tid >> 5;
    int lane = tid & 31;
    int r0 = blockIdx.x * BROWS;

    if (wid == 0) TCGEN05_ALLOC(smem_base + SM_TMEMPTR, 512);
    if (tid == 0) {
        MBARRIER_INIT(smem_base + SM_MBAR0, 1);
        MBARRIER_INIT(smem_base + SM_MBAR0 + 8, 1);
    }
    __syncthreads();
    uint32_t tmem_base;
    asm volatile("ld.shared.b32 %0, [%1];" : "=r"(tmem_base) : "r"(smem_base + SM_TMEMPTR));

    // ---- Prologue: load B chunk 0, convert+store A (f32->bf16) to TMEM ----
    load_B_chunk(smem, SM_BUF0, 0, tid);
    FENCE_PROXY_ASYNC();

    if (tid < 128) {
        const float* arow = E + (size_t)(r0 + tid) * DEMB;
        uint32_t warp_off = (uint32_t)(tid >> 5) << 21;
#pragma unroll 1
        for (int bt = 0; bt < 4; bt++) {
            uint32_t regs[64];
#pragma unroll
            for (int i = 0; i < 32; i++) {
                float4 v = ((const float4*)(arow + bt * 128))[i];
                __nv_bfloat162 h0 = __float22bfloat162_rn(make_float2(v.x, v.y));
                __nv_bfloat162 h1 = __float22bfloat162_rn(make_float2(v.z, v.w));
                regs[2 * i]     = *(uint32_t*)&h0;
                regs[2 * i + 1] = *(uint32_t*)&h1;
            }
            TCGEN05_ST_X64(tmem_base + TM_A + bt * 64 + warp_off, regs);
        }
        TCGEN05_WAIT_ST();
        TCGEN05_FENCE_BEFORE();
    }
    __syncthreads();

    float wabs = fabsf(wp[0]);
    float bb = bp[0];
    int half = wid >> 2;                   // 0: cols 0-31 of chunk, 1: cols 32-63
    int myrow = ((wid & 3) << 5) + lane;   // TMEM lane = A-tile row
    int grow = r0 + myrow;
    int spk = grow >> 3;                   // own-speaker column (M=8)
    float dval = fmaf(wabs, g_diag[grow], bb);
    float ssum = 0.f;

    // Issue MMA chunk 0
    if (wid == 0) {
        TCGEN05_FENCE_AFTER();
        if (elect_one()) {
            uint64_t bdesc = SMEM_DESC_BASE | (((uint64_t)(smem_base + SM_BUF0) >> 4) & 0x3FFF);
#pragma unroll
            for (int s = 0; s < KSTEPS; s++) {
                uint64_t bd = bdesc + (uint64_t)(((s >> 2) << 9) + ((s & 3) << 1));
                TCGEN05_MMA_F16(tmem_base + TM_D0, tmem_base + TM_A + s * 8, bd, MMA_IDESC, s > 0);
            }
            TCGEN05_COMMIT(smem_base + SM_MBAR0);
        }
    }

    // ---- Main pipelined loop: B-load(c+1) || MMA(c); then issue MMA(c+1); epi(c)
#pragma unroll 1
    for (int c = 0; c < NCHUNK; c++) {
        int cb = c & 1;
        if (c + 1 < NCHUNK) {
            load_B_chunk(smem, SM_BUF0 + ((c + 1) & 1) * 65536, c + 1, tid);
            FENCE_PROXY_ASYNC();
        }
        __syncthreads();

        MBARRIER_WAIT_PARITY(smem_base + SM_MBAR0 + 8 * cb, (c >> 1) & 1);
        TCGEN05_FENCE_AFTER();

        if (c + 1 < NCHUNK && wid == 0) {
            if (elect_one()) {
                int nb = (c + 1) & 1;
                uint64_t bdesc = SMEM_DESC_BASE |
                    (((uint64_t)(smem_base + SM_BUF0 + nb * 65536) >> 4) & 0x3FFF);
                uint32_t dt = tmem_base + TM_D0 + nb * 64;
#pragma unroll
                for (int s = 0; s < KSTEPS; s++) {
                    uint64_t bd = bdesc + (uint64_t)(((s >> 2) << 9) + ((s & 3) << 1));
                    TCGEN05_MMA_F16(dt, tmem_base + TM_A + s * 8, bd, MMA_IDESC, s > 0);
                }
                TCGEN05_COMMIT(smem_base + SM_MBAR0 + 8 * nb);
            }
        }

        // Epilogue chunk c: each thread owns one row, 32 columns
        uint32_t d[32];
        TCGEN05_LD_X32(d, tmem_base + TM_D0 + cb * 64 + half * 32);
        TCGEN05_WAIT_LD();
        int colbase = c * NB + half * 32;
#pragma unroll
        for (int j = 0; j < 32; j++) {
            float z = fmaf(wabs, __uint_as_float(d[j]), bb);
            z = (colbase + j == spk) ? dval : z;   // exact fp32 diagonal
            ssum += __expf(z);                      // z bounded in [-15, 5]
        }
        TCGEN05_FENCE_BEFORE();
    }

    // ---- Combine halves, per-row loss, block reduce ----
    float* red = (float*)(smem + SM_RED);
    red[half * 128 + myrow] = ssum;
    __syncthreads();

    if (wid < 4) {
        float total = red[myrow] + red[128 + myrow];
        float lr = logf(total) - dval;             // logsumexp - own logit
#pragma unroll
        for (int off = 16; off > 0; off >>= 1)
            lr += __shfl_xor_sync(0xffffffffu, lr, off);
        if (lane == 0) ((float*)(smem + SM_WS))[wid] = lr;
    }
    __syncthreads();
    if (tid == 0) {
        float* ws = (float*)(smem + SM_WS);
        atomicAdd(out, (ws[0] + ws[1] + ws[2] + ws[3]) * (1.0f / (float)NMROWS));
        MBARRIER_INVAL(smem_base + SM_MBAR0);
        MBARRIER_INVAL(smem_base + SM_MBAR0 + 8);
    }
    __syncthreads();
    if (wid == 0) {
        TCGEN05_RELINQUISH();
        TCGEN05_DEALLOC(tmem_base, 512);
    }
#else
    // ---------------- portable SIMT fallback (round-3 design) ----------------
    float (*As)[132] = (float (*)[132])(smem);                 // [16][132]
    float (*Bs)[132] = (float (*)[132])(smem + 16 * 132 * 4);  // [16][132]
    float* red = (float*)(smem + 2 * 16 * 132 * 4);            // [16]

    int tid = threadIdx.x;
    int tx = tid & 15;
    int ty = tid >> 4;
    int r0 = blockIdx.x * BROWS;
    int rowbase = r0 + ty * 8;

    float wabs = fabsf(wp[0]);
    float bb = bp[0];

    float dval[8];
#pragma unroll
    for (int i = 0; i < 8; i++) dval[i] = fmaf(wabs, g_diag[rowbase + i], bb);

    float mrun[8], srun[8];
#pragma unroll
    for (int i = 0; i < 8; i++) { mrun[i] = -1e30f; srun[i] = 0.f; }

    for (int c0 = 0; c0 < NSPK; c0 += 128) {
        float acc[8][8];
#pragma unroll
        for (int i = 0; i < 8; i++)
#pragma unroll
            for (int j = 0; j < 8; j++) acc[i][j] = 0.f;

        for (int k0 = 0; k0 < DEMB; k0 += 16) {
#pragma unroll
            for (int j = 0; j < 2; j++) {
                int i4 = tid + j * 256;
                int row = i4 >> 2;
                int c4 = i4 & 3;
                float4 va = *(const float4*)(E + (size_t)(r0 + row) * DEMB + k0 + c4 * 4);
                As[c4 * 4 + 0][row] = va.x;
                As[c4 * 4 + 1][row] = va.y;
                As[c4 * 4 + 2][row] = va.z;
                As[c4 * 4 + 3][row] = va.w;
                // centroids are bf16 scratch now; widen to f32
                uint2 ub = *(const uint2*)(g_cent_bf + (size_t)(c0 + row) * DEMB + k0 + c4 * 4);
                __nv_bfloat162 b0 = *(__nv_bfloat162*)&ub.x;
                __nv_bfloat162 b1 = *(__nv_bfloat162*)&ub.y;
                float2 f0 = __bfloat1622float2(b0);
                float2 f1 = __bfloat1622float2(b1);
                Bs[c4 * 4 + 0][row] = f0.x;
                Bs[c4 * 4 + 1][row] = f0.y;
                Bs[c4 * 4 + 2][row] = f1.x;
                Bs[c4 * 4 + 3][row] = f1.y;
            }
            __syncthreads();

#pragma unroll
            for (int kk = 0; kk < 16; kk++) {
                float4 a0 = *(const float4*)(&As[kk][ty * 8]);
                float4 a1 = *(const float4*)(&As[kk][ty * 8 + 4]);
                float4 b0 = *(const float4*)(&Bs[kk][tx * 8]);
                float4 b1 = *(const float4*)(&Bs[kk][tx * 8 + 4]);
                float av[8] = {a0.x, a0.y, a0.z, a0.w, a1.x, a1.y, a1.z, a1.w};
                float bv[8] = {b0.x, b0.y, b0.z, b0.w, b1.x, b1.y, b1.z, b1.w};
#pragma unroll
                for (int i = 0; i < 8; i++)
#pragma unroll
                    for (int j = 0; j < 8; j++) acc[i][j] = fmaf(av[i], bv[j], acc[i][j]);
            }
            __syncthreads();
        }

        int colbase = c0 + tx * 8;
#pragma unroll
        for (int i = 0; i < 8; i++) {
            int spk = (rowbase + i) >> 3;
            float z[8];
#pragma unroll
            for (int j = 0; j < 8; j++) z[j] = fmaf(wabs, acc[i][j], bb);
            int dcol = spk - colbase;
            if (dcol >= 0 && dcol < 8) z[dcol] = dval[i];

            float tm = z[0];
#pragma unroll
            for (int j = 1; j < 8; j++) tm = fmaxf(tm, z[j]);
#pragma unroll
            for (int off = 8; off > 0; off >>= 1)
                tm = fmaxf(tm, __shfl_xor_sync(0xffffffffu, tm, off));

            float nm = fmaxf(mrun[i], tm);
            float ts = 0.f;
#pragma unroll
            for (int j = 0; j < 8; j++) ts += __expf(z[j] - nm);
#pragma unroll
            for (int off = 8; off > 0; off >>= 1)
                ts += __shfl_xor_sync(0xffffffffu, ts, off);

            srun[i] = srun[i] * __expf(mrun[i] - nm) + ts;
            mrun[i] = nm;
        }
    }

    if (tx == 0) {
        float lsum = 0.f;
#pragma unroll
        for (int i = 0; i < 8; i++) lsum += logf(srun[i]) + mrun[i] - dval[i];
        red[ty] = lsum;
    }
    __syncthreads();
    if (tid == 0) {
        float t = 0.f;
#pragma unroll
        for (int k = 0; k < 16; k++) t += red[k];
        atomicAdd(out, t * (1.0f / (float)NMROWS));
    }
#endif
}

// ===========================================================================
extern "C" void kernel_launch(void* const* d_in, const int* in_sizes, int n_in,
                              void* d_out, int out_size) {
    const float* E = (const float*)d_in[0];
    const float* w = (const float*)d_in[1];
    const float* b = (const float*)d_in[2];
    float* out = (float*)d_out;

    cudaFuncSetAttribute(gemm_loss_kernel,
                         cudaFuncAttributeMaxDynamicSharedMemorySize, SMEM_TOTAL);

    centroid_kernel<<<256, 256>>>(E, out);
    gemm_loss_kernel<<<NMROWS / BROWS, 256, SMEM_TOTAL>>>(E, w, b, out);
}

// round 13
// speedup vs baseline: 16.1272x; 1.0834x over previous
#include <cuda_runtime.h>
#include <cuda_bf16.h>
#include <math.h>
#include <stdint.h>

// Problem constants (fixed by setup_inputs)
#define NSPK 2048
#define MUTT 8
#define DEMB 512
#define NMROWS (NSPK * MUTT)   // 16384

// tcgen05 is sm_103a/sm_100a arch-SPECIFIC; gate on arch-feature macros so the
// family-portable compute_103 pass compiles the SIMT fallback instead.
#if defined(__CUDA_ARCH__) && \
    (defined(__CUDA_ARCH_FEAT_SM103_ALL) || defined(__CUDA_ARCH_FEAT_SM100_ALL) || \
     defined(__CUDA_ARCH_FEAT_SM101_ALL))
#define USE_TCGEN05 1
#else
#define USE_TCGEN05 0
#endif

// Scratch: bf16 normalized centroids, fp32 leave-one-out diagonal sims
__device__ __nv_bfloat16 g_cent_bf[NSPK * DEMB];
__device__ float g_diag[NMROWS];

// ===========================================================================
// PTX helpers
// ===========================================================================
__device__ __forceinline__ uint32_t smem_u32(const void* p) {
    uint32_t a;
    asm("{ .reg .u64 t; cvta.to.shared.u64 t, %1; cvt.u32.u64 %0, t; }"
        : "=r"(a) : "l"(p));
    return a;
}

#if USE_TCGEN05
__device__ __forceinline__ uint32_t elect_one() {
    uint32_t p;
    asm volatile("{\n\t.reg .pred p;\n\telect.sync _|p, 0xFFFFFFFF;\n\t"
                 "selp.b32 %0, 1, 0, p;\n\t}" : "=r"(p));
    return p;
}
__device__ __forceinline__ float ex2f(float x) {
    float r;
    asm("ex2.approx.f32 %0, %1;" : "=f"(r) : "f"(x));
    return r;
}

#define TCGEN05_ALLOC(smem_addr, nCols) \
    asm volatile("tcgen05.alloc.cta_group::1.sync.aligned.shared::cta.b32 [%0], %1;" \
                 :: "r"((uint32_t)(smem_addr)), "r"((uint32_t)(nCols)) : "memory")
#define TCGEN05_DEALLOC(tmem, nCols) \
    asm volatile("tcgen05.dealloc.cta_group::1.sync.aligned.b32 %0, %1;" \
                 :: "r"(tmem), "r"((uint32_t)(nCols)))
#define TCGEN05_RELINQUISH() \
    asm volatile("tcgen05.relinquish_alloc_permit.cta_group::1.sync.aligned;")
#define TCGEN05_WAIT_ST() asm volatile("tcgen05.wait::st.sync.aligned;" ::: "memory")
#define TCGEN05_WAIT_LD() asm volatile("tcgen05.wait::ld.sync.aligned;" ::: "memory")
#define TCGEN05_FENCE_BEFORE() asm volatile("tcgen05.fence::before_thread_sync;" ::: "memory")
#define TCGEN05_FENCE_AFTER()  asm volatile("tcgen05.fence::after_thread_sync;" ::: "memory")
#define FENCE_PROXY_ASYNC() asm volatile("fence.proxy.async.shared::cta;" ::: "memory")
#define TCGEN05_COMMIT(mbar) \
    asm volatile("tcgen05.commit.cta_group::1.mbarrier::arrive::one.shared::cluster.b64 [%0];" \
                 :: "r"((uint32_t)(mbar)) : "memory")
#define MBARRIER_INIT(mbar, cnt) \
    asm volatile("mbarrier.init.shared.b64 [%0], %1;" \
                 :: "r"((uint32_t)(mbar)), "r"((uint32_t)(cnt)) : "memory")
#define MBARRIER_INVAL(mbar) \
    asm volatile("mbarrier.inval.shared.b64 [%0];" :: "r"((uint32_t)(mbar)) : "memory")

#define MBARRIER_WAIT_PARITY(mbar, parity) do {                                   \
    uint32_t _m = (uint32_t)(mbar); uint32_t _p = (uint32_t)(parity);             \
    asm volatile(                                                                 \
        "{\n\t.reg .pred P1;\n\t"                                                 \
        "WAIT_LOOP_%=:\n\t"                                                       \
        "mbarrier.try_wait.parity.acquire.cta.shared::cta.b64 P1, [%0], %1, 0x989680;\n\t" \
        "@P1 bra.uni WAIT_DONE_%=;\n\t"                                           \
        "bra.uni WAIT_LOOP_%=;\n\t"                                               \
        "WAIT_DONE_%=:\n\t}"                                                      \
        :: "r"(_m), "r"(_p) : "memory");                                          \
} while (0)

#define TCGEN05_MMA_F16(d_tmem, a_tmem, b_desc, idesc, enable_d) do {             \
    uint32_t _en = (enable_d) ? 1u : 0u; uint32_t _z = 0u;                        \
    asm volatile(                                                                 \
        "{\n\t.reg .pred p;\n\tsetp.ne.u32 p, %6, 0;\n\t"                         \
        "tcgen05.mma.cta_group::1.kind::f16 [%0], [%1], %2, %3, "                 \
        "{%4, %4, %4, %4}, p;\n\t}"                                               \
        :: "r"(d_tmem), "r"(a_tmem), "l"(b_desc), "r"(idesc),                     \
           "r"(_z), "r"(_z), "r"(_en) : "memory");                                \
} while (0)

#define TCGEN05_ST_X64(tmem_addr, r)                                              \
    asm volatile("tcgen05.st.sync.aligned.32x32b.x64.b32 [%0], "                  \
        "{%1, %2, %3, %4, %5, %6, %7, %8, "                                       \
        " %9, %10, %11, %12, %13, %14, %15, %16, "                                \
        " %17, %18, %19, %20, %21, %22, %23, %24, "                               \
        " %25, %26, %27, %28, %29, %30, %31, %32, "                               \
        " %33, %34, %35, %36, %37, %38, %39, %40, "                               \
        " %41, %42, %43, %44, %45, %46, %47, %48, "                               \
        " %49, %50, %51, %52, %53, %54, %55, %56, "                               \
        " %57, %58, %59, %60, %61, %62, %63, %64};"                               \
        :: "r"(tmem_addr),                                                        \
           "r"((r)[0]),  "r"((r)[1]),  "r"((r)[2]),  "r"((r)[3]),                 \
           "r"((r)[4]),  "r"((r)[5]),  "r"((r)[6]),  "r"((r)[7]),                 \
           "r"((r)[8]),  "r"((r)[9]),  "r"((r)[10]), "r"((r)[11]),                \
           "r"((r)[12]), "r"((r)[13]), "r"((r)[14]), "r"((r)[15]),                \
           "r"((r)[16]), "r"((r)[17]), "r"((r)[18]), "r"((r)[19]),                \
           "r"((r)[20]), "r"((r)[21]), "r"((r)[22]), "r"((r)[23]),                \
           "r"((r)[24]), "r"((r)[25]), "r"((r)[26]), "r"((r)[27]),                \
           "r"((r)[28]), "r"((r)[29]), "r"((r)[30]), "r"((r)[31]),                \
           "r"((r)[32]), "r"((r)[33]), "r"((r)[34]), "r"((r)[35]),                \
           "r"((r)[36]), "r"((r)[37]), "r"((r)[38]), "r"((r)[39]),                \
           "r"((r)[40]), "r"((r)[41]), "r"((r)[42]), "r"((r)[43]),                \
           "r"((r)[44]), "r"((r)[45]), "r"((r)[46]), "r"((r)[47]),                \
           "r"((r)[48]), "r"((r)[49]), "r"((r)[50]), "r"((r)[51]),                \
           "r"((r)[52]), "r"((r)[53]), "r"((r)[54]), "r"((r)[55]),                \
           "r"((r)[56]), "r"((r)[57]), "r"((r)[58]), "r"((r)[59]),                \
           "r"((r)[60]), "r"((r)[61]), "r"((r)[62]), "r"((r)[63])                 \
        : "memory")

#define TCGEN05_LD_X32(r, tmem_addr)                                              \
    asm volatile("tcgen05.ld.sync.aligned.32x32b.x32.b32 "                        \
        "{%0, %1, %2, %3, %4, %5, %6, %7, "                                       \
        " %8, %9, %10, %11, %12, %13, %14, %15, "                                 \
        " %16, %17, %18, %19, %20, %21, %22, %23, "                               \
        " %24, %25, %26, %27, %28, %29, %30, %31}, [%32];"                        \
        : "=r"((r)[0]),  "=r"((r)[1]),  "=r"((r)[2]),  "=r"((r)[3]),              \
          "=r"((r)[4]),  "=r"((r)[5]),  "=r"((r)[6]),  "=r"((r)[7]),              \
          "=r"((r)[8]),  "=r"((r)[9]),  "=r"((r)[10]), "=r"((r)[11]),             \
          "=r"((r)[12]), "=r"((r)[13]), "=r"((r)[14]), "=r"((r)[15]),             \
          "=r"((r)[16]), "=r"((r)[17]), "=r"((r)[18]), "=r"((r)[19]),             \
          "=r"((r)[20]), "=r"((r)[21]), "=r"((r)[22]), "=r"((r)[23]),             \
          "=r"((r)[24]), "=r"((r)[25]), "=r"((r)[26]), "=r"((r)[27]),             \
          "=r"((r)[28]), "=r"((r)[29]), "=r"((r)[30]), "=r"((r)[31])              \
        : "r"(tmem_addr))

// SMEM descriptor: SW128, version 1, SBO=64 (1024B per 8-row group), LBO=1
#define SMEM_DESC_BASE ((2ull << 61) | (1ull << 46) | (64ull << 32) | (1ull << 16))
#endif  // USE_TCGEN05

// ===========================================================================
// Kernel 1: centroids (bf16 out) + exact fp32 leave-one-out diag. Warp/speaker.
// ===========================================================================
__global__ void __launch_bounds__(256) centroid_kernel(const float* __restrict__ E,
                                                       float* __restrict__ out) {
    if (blockIdx.x == 0 && threadIdx.x == 0) out[0] = 0.0f;

    int warp = (blockIdx.x * blockDim.x + threadIdx.x) >> 5;
    int lane = threadIdx.x & 31;
    if (warp >= NSPK) return;

    const float* e = E + (size_t)warp * (MUTT * DEMB);

    float4 s[4];
#pragma unroll
    for (int c = 0; c < 4; c++) s[c] = make_float4(0.f, 0.f, 0.f, 0.f);

    float q[MUTT];
#pragma unroll
    for (int m = 0; m < MUTT; m++) {
        q[m] = 0.f;
#pragma unroll
        for (int c = 0; c < 4; c++) {
            float4 v = *(const float4*)(e + m * DEMB + c * 128 + lane * 4);
            s[c].x += v.x; s[c].y += v.y; s[c].z += v.z; s[c].w += v.w;
            q[m] += v.x * v.x + v.y * v.y + v.z * v.z + v.w * v.w;
        }
    }
    float p[MUTT];
#pragma unroll
    for (int m = 0; m < MUTT; m++) {
        p[m] = 0.f;
#pragma unroll
        for (int c = 0; c < 4; c++) {
            float4 v = *(const float4*)(e + m * DEMB + c * 128 + lane * 4);
            p[m] += v.x * s[c].x + v.y * s[c].y + v.z * s[c].z + v.w * s[c].w;
        }
    }
    float ns = 0.f;
#pragma unroll
    for (int c = 0; c < 4; c++)
        ns += s[c].x * s[c].x + s[c].y * s[c].y + s[c].z * s[c].z + s[c].w * s[c].w;

#pragma unroll
    for (int off = 16; off > 0; off >>= 1) {
#pragma unroll
        for (int m = 0; m < MUTT; m++) {
            p[m] += __shfl_xor_sync(0xffffffffu, p[m], off);
            q[m] += __shfl_xor_sync(0xffffffffu, q[m], off);
        }
        ns += __shfl_xor_sync(0xffffffffu, ns, off);
    }

    float inv = rsqrtf(ns);
#pragma unroll
    for (int c = 0; c < 4; c++) {
        __nv_bfloat162 h0 = __float22bfloat162_rn(make_float2(s[c].x * inv, s[c].y * inv));
        __nv_bfloat162 h1 = __float22bfloat162_rn(make_float2(s[c].z * inv, s[c].w * inv));
        uint32_t u0 = *(uint32_t*)&h0, u1 = *(uint32_t*)&h1;
        *(uint2*)(g_cent_bf + (size_t)warp * DEMB + c * 128 + lane * 4) = make_uint2(u0, u1);
    }
    if (lane < MUTT) {
        float pm = p[lane], qm = q[lane];
        g_diag[warp * MUTT + lane] = (pm - qm) * rsqrtf(ns - 2.f * pm + qm);
    }
}

// ===========================================================================
// Kernel 2 (grid 128, block 384, dynamic smem)
//   sm_103a: warp-specialized tcgen05 pipeline
//     warps 0-7  : epilogue consumers + MMA issue (warp 0 elect)
//     warps 8-11 : B-chunk loaders
//   B-ready handshake uses PARITY-SPLIT named barriers (4 for even chunks,
//   5 for odd) so loader arrivals can never overrun a barrier phase: a loader
//   reaches the same barrier id again only after the MMA commit of the chunk
//   two back, which itself requires consumers to have synced that id.
// ===========================================================================
#define BROWS 128
#define NB 64
#define NCHUNK (NSPK / NB)     // 32
#define KSTEPS (DEMB / 16)     // 32
#define MMA_IDESC 0x8100490u   // f32 acc, bf16 A/B, K-major, M=128, N=64
#define NTHREADS 384
#define LOG2E 1.4426950408889634f

// shared memory offsets
#define SM_TMEMPTR 0
#define SM_MBAR0   8
#define SM_BUF0    2048
#define SM_RED     (2048 + 131072)      // 256 floats
#define SM_WS      (SM_RED + 1024)      // 4 floats
#define SMEM_TOTAL (SM_WS + 64)

// TMEM columns: A = [0,256), D0 = [256,320), D1 = [320,384)
#define TM_A  0
#define TM_D0 256

__global__ void __launch_bounds__(NTHREADS, 1) gemm_loss_kernel(const float* __restrict__ E,
                                                                const float* __restrict__ wp,
                                                                const float* __restrict__ bp,
                                                                float* __restrict__ out) {
    extern __shared__ char smem[];
#if USE_TCGEN05
    uint32_t smem_base = smem_u32(smem);
    int tid = threadIdx.x;
    int wid = tid >> 5;
    int lane = tid & 31;
    int r0 = blockIdx.x * BROWS;

    if (wid == 0) TCGEN05_ALLOC(smem_base + SM_TMEMPTR, 512);
    if (tid == 0) {
        MBARRIER_INIT(smem_base + SM_MBAR0, 1);
        MBARRIER_INIT(smem_base + SM_MBAR0 + 8, 1);
    }
    __syncthreads();
    uint32_t tmem_base;
    asm volatile("ld.shared.b32 %0, [%1];" : "=r"(tmem_base) : "r"(smem_base + SM_TMEMPTR));

    if (wid >= 8) {
        // ---------------- loader warps (8-11): stream B chunks ----------------
        int ltid = tid - 256;
#pragma unroll 1
        for (int c = 0; c < NCHUNK; c++) {
            if (c >= 2) {
                // wait until the tensor unit finished reading buf[c&1] (chunk c-2)
                MBARRIER_WAIT_PARITY(smem_base + SM_MBAR0 + 8 * (c & 1),
                                     ((c - 2) >> 1) & 1);
            }
            const uint4* g = (const uint4*)(g_cent_bf + (size_t)c * NB * DEMB);
            char* buf = smem + SM_BUF0 + (c & 1) * 65536;
#pragma unroll
            for (int i = 0; i < 32; i++) {
                int lin = ltid + i * 128;            // uint4 index, 0..4095
                int brow = lin >> 6;                 // centroid row in chunk
                int kc = (lin & 63) << 3;            // bf16 k-col, multiple of 8
                uint32_t off = (uint32_t)((brow >> 3) + ((kc >> 6) << 3)) * 1024u
                             + (uint32_t)(brow & 7) * 128u + (uint32_t)(kc & 63) * 2u;
                off ^= ((off >> 3) & 0x70u);         // SW128 swizzle
                *(uint4*)(buf + off) = g[lin];
            }
            FENCE_PROXY_ASYNC();
            {
                int barid = 4 + (c & 1);
                asm volatile("bar.arrive %0, %1;" :: "r"(barid), "n"(NTHREADS) : "memory");
            }
        }
    } else {
        // ---------------- consumer warps (0-7) ----------------
        // Prologue: A (f32 -> bf16) into TMEM, threads 0-127 own one row each
        if (tid < 128) {
            const float* arow = E + (size_t)(r0 + tid) * DEMB;
            uint32_t warp_off = (uint32_t)(tid >> 5) << 21;
#pragma unroll 1
            for (int bt = 0; bt < 4; bt++) {
                uint32_t regs[64];
#pragma unroll
                for (int i = 0; i < 32; i++) {
                    float4 v = ((const float4*)(arow + bt * 128))[i];
                    __nv_bfloat162 h0 = __float22bfloat162_rn(make_float2(v.x, v.y));
                    __nv_bfloat162 h1 = __float22bfloat162_rn(make_float2(v.z, v.w));
                    regs[2 * i]     = *(uint32_t*)&h0;
                    regs[2 * i + 1] = *(uint32_t*)&h1;
                }
                TCGEN05_ST_X64(tmem_base + TM_A + bt * 64 + warp_off, regs);
            }
            TCGEN05_WAIT_ST();
            TCGEN05_FENCE_BEFORE();
        }
        asm volatile("bar.sync 3, 256;" ::: "memory");  // consumers: A in TMEM
        TCGEN05_FENCE_AFTER();

        float wabs = fabsf(wp[0]);
        float bb = bp[0];
        float wl = wabs * LOG2E;
        float bl = bb * LOG2E;
        int half = wid >> 2;                   // 0: cols 0-31, 1: cols 32-63
        int myrow = ((wid & 3) << 5) + lane;   // TMEM lane = A-tile row
        int grow = r0 + myrow;
        int spk = grow >> 3;                   // own-speaker column (M=8)
        float dval = fmaf(wabs, g_diag[grow], bb);   // exact, natural-log domain
        float dval_l = dval * LOG2E;
        float e_dval = ex2f(dval_l);
        float ssum = 0.f;

#pragma unroll 1
        for (int c = 0; c < NCHUNK; c++) {
            // B chunk c ready (parity-split handshake barrier)
            {
                int barid = 4 + (c & 1);
                asm volatile("bar.sync %0, %1;" :: "r"(barid), "n"(NTHREADS) : "memory");
            }
            // Issue MMA(c) ahead (tensor queue stays busy during epi(c-1))
            if (wid == 0) {
                if (elect_one()) {
                    uint64_t bdesc = SMEM_DESC_BASE |
                        (((uint64_t)(smem_base + SM_BUF0 + (c & 1) * 65536) >> 4) & 0x3FFF);
                    uint32_t dt = tmem_base + TM_D0 + (c & 1) * 64;
#pragma unroll
                    for (int s = 0; s < KSTEPS; s++) {
                        uint64_t bd = bdesc + (uint64_t)(((s >> 2) << 9) + ((s & 3) << 1));
                        TCGEN05_MMA_F16(dt, tmem_base + TM_A + s * 8, bd, MMA_IDESC, s > 0);
                    }
                    TCGEN05_COMMIT(smem_base + SM_MBAR0 + 8 * (c & 1));
                }
            }
            if (c > 0) {
                int pc = c - 1;
                MBARRIER_WAIT_PARITY(smem_base + SM_MBAR0 + 8 * (pc & 1), (pc >> 1) & 1);
                TCGEN05_FENCE_AFTER();
                uint32_t d[32];
                TCGEN05_LD_X32(d, tmem_base + TM_D0 + (pc & 1) * 64 + half * 32);
                TCGEN05_WAIT_LD();
                int colbase = pc * NB + half * 32;
                float s0 = 0.f, s1 = 0.f;
#pragma unroll
                for (int j = 0; j < 32; j += 2) {
                    s0 += ex2f(fmaf(wl, __uint_as_float(d[j]), bl));
                    s1 += ex2f(fmaf(wl, __uint_as_float(d[j + 1]), bl));
                }
                int dsel = spk - colbase;
                if (dsel >= 0 && dsel < 32) {   // replace own column by exact diag
                    s0 += e_dval - ex2f(fmaf(wl, __uint_as_float(d[dsel]), bl));
                }
                ssum += s0 + s1;
                TCGEN05_FENCE_BEFORE();
                asm volatile("bar.sync 2, 256;" ::: "memory");  // D buffer free
            }
        }
        // tail epilogue for chunk NCHUNK-1
        {
            int pc = NCHUNK - 1;
            MBARRIER_WAIT_PARITY(smem_base + SM_MBAR0 + 8 * (pc & 1), (pc >> 1) & 1);
            TCGEN05_FENCE_AFTER();
            uint32_t d[32];
            TCGEN05_LD_X32(d, tmem_base + TM_D0 + (pc & 1) * 64 + half * 32);
            TCGEN05_WAIT_LD();
            int colbase = pc * NB + half * 32;
            float s0 = 0.f, s1 = 0.f;
#pragma unroll
            for (int j = 0; j < 32; j += 2) {
                s0 += ex2f(fmaf(wl, __uint_as_float(d[j]), bl));
                s1 += ex2f(fmaf(wl, __uint_as_float(d[j + 1]), bl));
            }
            int dsel = spk - colbase;
            if (dsel >= 0 && dsel < 32) {
                s0 += e_dval - ex2f(fmaf(wl, __uint_as_float(d[dsel]), bl));
            }
            ssum += s0 + s1;
            TCGEN05_FENCE_BEFORE();
        }

        // combine halves, per-row loss, block reduce
        float* red = (float*)(smem + SM_RED);
        red[half * 128 + myrow] = ssum;
        asm volatile("bar.sync 2, 256;" ::: "memory");

        if (wid < 4) {
            float total = red[myrow] + red[128 + myrow];
            float lr = logf(total) - dval;          // logsumexp - own logit
#pragma unroll
            for (int off = 16; off > 0; off >>= 1)
                lr += __shfl_xor_sync(0xffffffffu, lr, off);
            if (lane == 0) ((float*)(smem + SM_WS))[wid] = lr;
        }
        asm volatile("bar.sync 2, 256;" ::: "memory");
        if (tid == 0) {
            float* ws = (float*)(smem + SM_WS);
            atomicAdd(out, (ws[0] + ws[1] + ws[2] + ws[3]) * (1.0f / (float)NMROWS));
        }
    }

    // full-CTA teardown
    __syncthreads();
    if (tid == 0) {
        MBARRIER_INVAL(smem_base + SM_MBAR0);
        MBARRIER_INVAL(smem_base + SM_MBAR0 + 8);
    }
    __syncthreads();
    if (wid == 0) {
        TCGEN05_RELINQUISH();
        TCGEN05_DEALLOC(tmem_base, 512);
    }
#else
    // ---------------- portable SIMT fallback (compile-only on GB300) ----------
    float (*As)[132] = (float (*)[132])(smem);                 // [16][132]
    float (*Bs)[132] = (float (*)[132])(smem + 16 * 132 * 4);  // [16][132]
    float* red = (float*)(smem + 2 * 16 * 132 * 4);            // [16]

    int tid = threadIdx.x;
    int tx = tid & 15;
    int ty = tid >> 4;
    int r0 = blockIdx.x * BROWS;
    int rowbase = r0 + ty * 8;
    bool active = tid < 256;

    float wabs = fabsf(wp[0]);
    float bb = bp[0];

    float dval[8];
#pragma unroll
    for (int i = 0; i < 8; i++)
        dval[i] = active ? fmaf(wabs, g_diag[rowbase + i], bb) : 0.f;

    float mrun[8], srun[8];
#pragma unroll
    for (int i = 0; i < 8; i++) { mrun[i] = -1e30f; srun[i] = 0.f; }

    for (int c0 = 0; c0 < NSPK; c0 += 128) {
        float acc[8][8];
#pragma unroll
        for (int i = 0; i < 8; i++)
#pragma unroll
            for (int j = 0; j < 8; j++) acc[i][j] = 0.f;

        for (int k0 = 0; k0 < DEMB; k0 += 16) {
            for (int i4 = tid; i4 < 512; i4 += NTHREADS) {
                int row = i4 >> 2;
                int c4 = i4 & 3;
                float4 va = *(const float4*)(E + (size_t)(r0 + row) * DEMB + k0 + c4 * 4);
                As[c4 * 4 + 0][row] = va.x;
                As[c4 * 4 + 1][row] = va.y;
                As[c4 * 4 + 2][row] = va.z;
                As[c4 * 4 + 3][row] = va.w;
                uint2 ub = *(const uint2*)(g_cent_bf + (size_t)(c0 + row) * DEMB + k0 + c4 * 4);
                __nv_bfloat162 b0 = *(__nv_bfloat162*)&ub.x;
                __nv_bfloat162 b1 = *(__nv_bfloat162*)&ub.y;
                float2 f0 = __bfloat1622float2(b0);
                float2 f1 = __bfloat1622float2(b1);
                Bs[c4 * 4 + 0][row] = f0.x;
                Bs[c4 * 4 + 1][row] = f0.y;
                Bs[c4 * 4 + 2][row] = f1.x;
                Bs[c4 * 4 + 3][row] = f1.y;
            }
            __syncthreads();

            if (active) {
#pragma unroll
                for (int kk = 0; kk < 16; kk++) {
                    float4 a0 = *(const float4*)(&As[kk][ty * 8]);
                    float4 a1 = *(const float4*)(&As[kk][ty * 8 + 4]);
                    float4 b0 = *(const float4*)(&Bs[kk][tx * 8]);
                    float4 b1 = *(const float4*)(&Bs[kk][tx * 8 + 4]);
                    float av[8] = {a0.x, a0.y, a0.z, a0.w, a1.x, a1.y, a1.z, a1.w};
                    float bv[8] = {b0.x, b0.y, b0.z, b0.w, b1.x, b1.y, b1.z, b1.w};
#pragma unroll
                    for (int i = 0; i < 8; i++)
#pragma unroll
                        for (int j = 0; j < 8; j++) acc[i][j] = fmaf(av[i], bv[j], acc[i][j]);
                }
            }
            __syncthreads();
        }

        if (active) {
            int colbase = c0 + tx * 8;
#pragma unroll
            for (int i = 0; i < 8; i++) {
                int spk = (rowbase + i) >> 3;
                float z[8];
#pragma unroll
                for (int j = 0; j < 8; j++) z[j] = fmaf(wabs, acc[i][j], bb);
                int dcol = spk - colbase;
                if (dcol >= 0 && dcol < 8) z[dcol] = dval[i];

                float tm = z[0];
#pragma unroll
                for (int j = 1; j < 8; j++) tm = fmaxf(tm, z[j]);
#pragma unroll
                for (int off = 8; off > 0; off >>= 1)
                    tm = fmaxf(tm, __shfl_xor_sync(0xffffffffu, tm, off));

                float nm = fmaxf(mrun[i], tm);
                float ts = 0.f;
#pragma unroll
                for (int j = 0; j < 8; j++) ts += __expf(z[j] - nm);
#pragma unroll
                for (int off = 8; off > 0; off >>= 1)
                    ts += __shfl_xor_sync(0xffffffffu, ts, off);

                srun[i] = srun[i] * __expf(mrun[i] - nm) + ts;
                mrun[i] = nm;
            }
        }
    }

    if (active && tx == 0) {
        float lsum = 0.f;
#pragma unroll
        for (int i = 0; i < 8; i++) lsum += logf(srun[i]) + mrun[i] - dval[i];
        red[ty] = lsum;
    }
    __syncthreads();
    if (tid == 0) {
        float t = 0.f;
#pragma unroll
        for (int k = 0; k < 16; k++) t += red[k];
        atomicAdd(out, t * (1.0f / (float)NMROWS));
    }
#endif
}

// ===========================================================================
extern "C" void kernel_launch(void* const* d_in, const int* in_sizes, int n_in,
                              void* d_out, int out_size) {
    const float* E = (const float*)d_in[0];
    const float* w = (const float*)d_in[1];
    const float* b = (const float*)d_in[2];
    float* out = (float*)d_out;

    cudaFuncSetAttribute(gemm_loss_kernel,
                         cudaFuncAttributeMaxDynamicSharedMemorySize, SMEM_TOTAL);

    centroid_kernel<<<256, 256>>>(E, out);
    gemm_loss_kernel<<<NMROWS / BROWS, NTHREADS, SMEM_TOTAL>>>(E, w, b, out);
}